// round 1
// baseline (speedup 1.0000x reference)
#include <cuda_runtime.h>

// Problem constants (fixed by the reference).
#define N_TOK 8192
#define DDIM  2048
#define MDIM  512
#define NEXP  4

// GEMM tiling
#define BM 128
#define BN 128
#define BK 16
#define TM 8
#define TN 8
// 256 threads: 16 (tx) x 16 (ty), each computes TM x TN = 8x8 outputs.

// Scratch (no cudaMalloc allowed): binning tables + hidden activations.
__device__ int   g_count[NEXP];
__device__ int   g_idx[NEXP * N_TOK];
__device__ float g_h[(size_t)N_TOK * MDIM];   // 16.8 MB

// ---------------- packed f32x2 helpers (sm_103a FFMA2 pipe) ----------------
__device__ __forceinline__ unsigned long long pk2(float lo, float hi) {
    unsigned long long r;
    asm("mov.b64 %0, {%1, %2};" : "=l"(r) : "f"(lo), "f"(hi));
    return r;
}
__device__ __forceinline__ void upk2(unsigned long long v, float& lo, float& hi) {
    asm("mov.b64 {%0, %1}, %2;" : "=f"(lo), "=f"(hi) : "l"(v));
}
__device__ __forceinline__ void fma2(unsigned long long& d, unsigned long long a,
                                     unsigned long long b) {
    asm("fma.rn.f32x2 %0, %1, %2, %0;" : "+l"(d) : "l"(a), "l"(b));
}

// ---------------- binning: detect domains dtype, bucket tokens -------------
// The reference declares domains as int64, but JAX without x64 silently emits
// int32. Detect from the data: if int64, the high 32-bit word of each element
// is 0 and low words are in [0,3]. We sample the first 4096 elements (stays
// in-bounds for both layouts).
__global__ void bin_kernel(const int* __restrict__ dom32) {
    __shared__ int cnt[NEXP];
    __shared__ int flag64;
    int tid = threadIdx.x;
    if (tid < NEXP) cnt[tid] = 0;
    if (tid == 0) flag64 = 1;
    __syncthreads();

    int bad = 0;
    for (int i = tid; i < 4096; i += blockDim.x) {
        int hi = dom32[2 * i + 1];
        int lo = dom32[2 * i];
        if (hi != 0 || lo < 0 || lo > 3) bad = 1;
    }
    if (bad) atomicExch(&flag64, 0);
    __syncthreads();
    bool is64 = (flag64 != 0);

    for (int n = tid; n < N_TOK; n += blockDim.x) {
        int e = is64 ? dom32[2 * n] : dom32[n];
        int pos = atomicAdd(&cnt[e], 1);
        g_idx[e * N_TOK + pos] = n;
    }
    __syncthreads();
    if (tid < NEXP) g_count[tid] = cnt[tid];
}

// ---------------- GEMM1: h = relu(Xg @ W1[e]^T + b1[e]) --------------------
// grid: (MDIM/BN=4, N_TOK/BM=64, NEXP)
__global__ __launch_bounds__(256)
void gemm1_kernel(const float* __restrict__ X, const float* __restrict__ W1,
                  const float* __restrict__ b1) {
    __shared__ float As[BK][BM];
    __shared__ float Bs[BK][BN];
    __shared__ int   toks[BM];

    const int e = blockIdx.z;
    const int cnt = g_count[e];
    const int row0 = blockIdx.y * BM;
    if (row0 >= cnt) return;

    const int tid = threadIdx.x;
    if (tid < BM) {
        int slot = row0 + tid;
        toks[tid] = (slot < cnt) ? g_idx[e * N_TOK + slot] : -1;
    }
    __syncthreads();

    const int n0 = blockIdx.x * BN;
    const float* Wb = W1 + (size_t)e * MDIM * DDIM;

    const int lr = tid >> 2;          // 0..63 (row within half-tile)
    const int lc = (tid & 3) * 4;     // 0,4,8,12 (k offset, float4)
    const int tx = tid & 15;
    const int ty = tid >> 4;

    const int tokA0 = toks[lr];
    const int tokA1 = toks[lr + 64];
    const float* a0p = X + (size_t)(tokA0 < 0 ? 0 : tokA0) * DDIM + lc;
    const float* a1p = X + (size_t)(tokA1 < 0 ? 0 : tokA1) * DDIM + lc;
    const float* b0p = Wb + (size_t)(n0 + lr) * DDIM + lc;
    const float* b1p = Wb + (size_t)(n0 + lr + 64) * DDIM + lc;

    unsigned long long acc[TM][TN / 2];
#pragma unroll
    for (int i = 0; i < TM; i++)
#pragma unroll
        for (int j = 0; j < TN / 2; j++) acc[i][j] = 0ULL;

    for (int k0 = 0; k0 < DDIM; k0 += BK) {
        float4 va0 = make_float4(0.f, 0.f, 0.f, 0.f);
        float4 va1 = va0;
        if (tokA0 >= 0) va0 = *(const float4*)(a0p + k0);
        if (tokA1 >= 0) va1 = *(const float4*)(a1p + k0);
        float4 vb0 = *(const float4*)(b0p + k0);
        float4 vb1 = *(const float4*)(b1p + k0);

        __syncthreads();   // previous iteration's reads complete
        As[lc + 0][lr] = va0.x; As[lc + 1][lr] = va0.y;
        As[lc + 2][lr] = va0.z; As[lc + 3][lr] = va0.w;
        As[lc + 0][lr + 64] = va1.x; As[lc + 1][lr + 64] = va1.y;
        As[lc + 2][lr + 64] = va1.z; As[lc + 3][lr + 64] = va1.w;
        Bs[lc + 0][lr] = vb0.x; Bs[lc + 1][lr] = vb0.y;
        Bs[lc + 2][lr] = vb0.z; Bs[lc + 3][lr] = vb0.w;
        Bs[lc + 0][lr + 64] = vb1.x; Bs[lc + 1][lr + 64] = vb1.y;
        Bs[lc + 2][lr + 64] = vb1.z; Bs[lc + 3][lr + 64] = vb1.w;
        __syncthreads();

#pragma unroll
        for (int kk = 0; kk < BK; kk++) {
            float4 fa0 = *(const float4*)&As[kk][ty * TM];
            float4 fa1 = *(const float4*)&As[kk][ty * TM + 4];
            float4 fb0 = *(const float4*)&Bs[kk][tx * TN];
            float4 fb1 = *(const float4*)&Bs[kk][tx * TN + 4];
            unsigned long long bp[4] = {pk2(fb0.x, fb0.y), pk2(fb0.z, fb0.w),
                                        pk2(fb1.x, fb1.y), pk2(fb1.z, fb1.w)};
            float av[TM] = {fa0.x, fa0.y, fa0.z, fa0.w, fa1.x, fa1.y, fa1.z, fa1.w};
#pragma unroll
            for (int i = 0; i < TM; i++) {
                unsigned long long ap = pk2(av[i], av[i]);
                fma2(acc[i][0], ap, bp[0]);
                fma2(acc[i][1], ap, bp[1]);
                fma2(acc[i][2], ap, bp[2]);
                fma2(acc[i][3], ap, bp[3]);
            }
        }
    }

    const float* bb = b1 + e * MDIM + n0 + tx * TN;
#pragma unroll
    for (int i = 0; i < TM; i++) {
        int tok = toks[ty * TM + i];
        if (tok < 0) continue;
        float* hrow = g_h + (size_t)tok * MDIM + n0 + tx * TN;
#pragma unroll
        for (int j = 0; j < TN / 2; j++) {
            float lo, hi;
            upk2(acc[i][j], lo, hi);
            lo += bb[2 * j];
            hi += bb[2 * j + 1];
            hrow[2 * j]     = fmaxf(lo, 0.f);
            hrow[2 * j + 1] = fmaxf(hi, 0.f);
        }
    }
}

// ---------------- GEMM2: out = x + h @ W2[e]^T + b2[e] ---------------------
// grid: (DDIM/BN=16, N_TOK/BM=64, NEXP)
__global__ __launch_bounds__(256)
void gemm2_kernel(const float* __restrict__ X, const float* __restrict__ W2,
                  const float* __restrict__ b2, float* __restrict__ out) {
    __shared__ float As[BK][BM];
    __shared__ float Bs[BK][BN];
    __shared__ int   toks[BM];

    const int e = blockIdx.z;
    const int cnt = g_count[e];
    const int row0 = blockIdx.y * BM;
    if (row0 >= cnt) return;

    const int tid = threadIdx.x;
    if (tid < BM) {
        int slot = row0 + tid;
        toks[tid] = (slot < cnt) ? g_idx[e * N_TOK + slot] : -1;
    }
    __syncthreads();

    const int n0 = blockIdx.x * BN;
    const float* Wb = W2 + (size_t)e * DDIM * MDIM;

    const int lr = tid >> 2;
    const int lc = (tid & 3) * 4;
    const int tx = tid & 15;
    const int ty = tid >> 4;

    const int tokA0 = toks[lr];
    const int tokA1 = toks[lr + 64];
    const float* a0p = g_h + (size_t)(tokA0 < 0 ? 0 : tokA0) * MDIM + lc;
    const float* a1p = g_h + (size_t)(tokA1 < 0 ? 0 : tokA1) * MDIM + lc;
    const float* b0p = Wb + (size_t)(n0 + lr) * MDIM + lc;
    const float* b1p = Wb + (size_t)(n0 + lr + 64) * MDIM + lc;

    unsigned long long acc[TM][TN / 2];
#pragma unroll
    for (int i = 0; i < TM; i++)
#pragma unroll
        for (int j = 0; j < TN / 2; j++) acc[i][j] = 0ULL;

    for (int k0 = 0; k0 < MDIM; k0 += BK) {
        float4 va0 = make_float4(0.f, 0.f, 0.f, 0.f);
        float4 va1 = va0;
        if (tokA0 >= 0) va0 = *(const float4*)(a0p + k0);
        if (tokA1 >= 0) va1 = *(const float4*)(a1p + k0);
        float4 vb0 = *(const float4*)(b0p + k0);
        float4 vb1 = *(const float4*)(b1p + k0);

        __syncthreads();
        As[lc + 0][lr] = va0.x; As[lc + 1][lr] = va0.y;
        As[lc + 2][lr] = va0.z; As[lc + 3][lr] = va0.w;
        As[lc + 0][lr + 64] = va1.x; As[lc + 1][lr + 64] = va1.y;
        As[lc + 2][lr + 64] = va1.z; As[lc + 3][lr + 64] = va1.w;
        Bs[lc + 0][lr] = vb0.x; Bs[lc + 1][lr] = vb0.y;
        Bs[lc + 2][lr] = vb0.z; Bs[lc + 3][lr] = vb0.w;
        Bs[lc + 0][lr + 64] = vb1.x; Bs[lc + 1][lr + 64] = vb1.y;
        Bs[lc + 2][lr + 64] = vb1.z; Bs[lc + 3][lr + 64] = vb1.w;
        __syncthreads();

#pragma unroll
        for (int kk = 0; kk < BK; kk++) {
            float4 fa0 = *(const float4*)&As[kk][ty * TM];
            float4 fa1 = *(const float4*)&As[kk][ty * TM + 4];
            float4 fb0 = *(const float4*)&Bs[kk][tx * TN];
            float4 fb1 = *(const float4*)&Bs[kk][tx * TN + 4];
            unsigned long long bp[4] = {pk2(fb0.x, fb0.y), pk2(fb0.z, fb0.w),
                                        pk2(fb1.x, fb1.y), pk2(fb1.z, fb1.w)};
            float av[TM] = {fa0.x, fa0.y, fa0.z, fa0.w, fa1.x, fa1.y, fa1.z, fa1.w};
#pragma unroll
            for (int i = 0; i < TM; i++) {
                unsigned long long ap = pk2(av[i], av[i]);
                fma2(acc[i][0], ap, bp[0]);
                fma2(acc[i][1], ap, bp[1]);
                fma2(acc[i][2], ap, bp[2]);
                fma2(acc[i][3], ap, bp[3]);
            }
        }
    }

    const float* bb = b2 + e * DDIM + n0 + tx * TN;
#pragma unroll
    for (int i = 0; i < TM; i++) {
        int tok = toks[ty * TM + i];
        if (tok < 0) continue;
        const float* xrow = X + (size_t)tok * DDIM + n0 + tx * TN;
        float* orow = out + (size_t)tok * DDIM + n0 + tx * TN;
#pragma unroll
        for (int j = 0; j < TN / 2; j++) {
            float lo, hi;
            upk2(acc[i][j], lo, hi);
            orow[2 * j]     = xrow[2 * j]     + lo + bb[2 * j];
            orow[2 * j + 1] = xrow[2 * j + 1] + hi + bb[2 * j + 1];
        }
    }
}

// ---------------- launch ----------------------------------------------------
extern "C" void kernel_launch(void* const* d_in, const int* in_sizes, int n_in,
                              void* d_out, int out_size) {
    const float* x   = (const float*)d_in[0];
    const int*   dom = (const int*)d_in[1];   // int32 or int64; detected on-device
    const float* W1  = (const float*)d_in[2];
    const float* b1  = (const float*)d_in[3];
    const float* W2  = (const float*)d_in[4];
    const float* b2  = (const float*)d_in[5];
    float* out = (float*)d_out;

    bin_kernel<<<1, 256>>>(dom);
    gemm1_kernel<<<dim3(MDIM / BN, N_TOK / BM, NEXP), 256>>>(x, W1, b1);
    gemm2_kernel<<<dim3(DDIM / BN, N_TOK / BM, NEXP), 256>>>(x, W2, b2, out);
}

// round 6
// speedup vs baseline: 2.0581x; 2.0581x over previous
#include <cuda_runtime.h>
#include <cuda_bf16.h>
#include <cstdint>

#define N_TOK 8192
#define DDIM  2048
#define MDIM  512
#define NEXP  4

#define BMT 128           // token rows per CTA
#define BNT 128           // output cols per CTA
#define BK  32            // K elems per stage
#define PAD 40            // padded smem row length (elems) -> conflict-free frags
#define TILEB (128 * PAD * 2)   // bytes per tile (10240)
#define THREADS 256
#define SMEM_BYTES (1024 + 2 * 4 * TILEB)   // toks + 2 stages x 4 tiles = 82944

// ---------------- device scratch (no cudaMalloc allowed) -------------------
__device__ int g_count[NEXP];
__device__ int g_idx[NEXP * N_TOK];
__device__ __nv_bfloat16 g_xh[(size_t)N_TOK * DDIM];
__device__ __nv_bfloat16 g_xl[(size_t)N_TOK * DDIM];
__device__ __nv_bfloat16 g_w1h[(size_t)NEXP * MDIM * DDIM];
__device__ __nv_bfloat16 g_w1l[(size_t)NEXP * MDIM * DDIM];
__device__ __nv_bfloat16 g_w2h[(size_t)NEXP * DDIM * MDIM];
__device__ __nv_bfloat16 g_w2l[(size_t)NEXP * DDIM * MDIM];
__device__ __nv_bfloat16 g_hh[(size_t)N_TOK * MDIM];
__device__ __nv_bfloat16 g_hl[(size_t)N_TOK * MDIM];

// ---------------- helpers ---------------------------------------------------
__device__ __forceinline__ uint32_t smem_u32(const void* p) {
    uint32_t a;
    asm("{ .reg .u64 t; cvta.to.shared.u64 t, %1; cvt.u32.u64 %0, t; }"
        : "=r"(a) : "l"(p));
    return a;
}
__device__ __forceinline__ void cp16(uint32_t dst, const void* src) {
    asm volatile("cp.async.cg.shared.global [%0], [%1], 16;"
                 :: "r"(dst), "l"(src) : "memory");
}
__device__ __forceinline__ void cp_commit() {
    asm volatile("cp.async.commit_group;" ::: "memory");
}
__device__ __forceinline__ void cp_wait0() {
    asm volatile("cp.async.wait_group 0;" ::: "memory");
}
__device__ __forceinline__ void cp_wait1() {
    asm volatile("cp.async.wait_group 1;" ::: "memory");
}
// mma.sync m16n8k16 bf16 -> f32 (sm_80+ feature set; valid on plain sm_103)
__device__ __forceinline__ void mma16816(float* c, const uint32_t* a,
                                         const uint32_t* b) {
    asm volatile(
        "mma.sync.aligned.m16n8k16.row.col.f32.bf16.bf16.f32 "
        "{%0,%1,%2,%3}, {%4,%5,%6,%7}, {%8,%9}, {%0,%1,%2,%3};"
        : "+f"(c[0]), "+f"(c[1]), "+f"(c[2]), "+f"(c[3])
        : "r"(a[0]), "r"(a[1]), "r"(a[2]), "r"(a[3]), "r"(b[0]), "r"(b[1]));
}
// packed bf16 pair at (row, col..col+1), col even
__device__ __forceinline__ uint32_t lpair(const char* base, int row, int col) {
    return *(const uint32_t*)(base + ((size_t)row * PAD + col) * 2);
}
__device__ __forceinline__ uint32_t pack_bf(__nv_bfloat16 a, __nv_bfloat16 b) {
    return (uint32_t)__bfloat16_as_ushort(a) | ((uint32_t)__bfloat16_as_ushort(b) << 16);
}

// ---------------- binning (domains dtype auto-detect) ----------------------
__global__ void bin_kernel(const int* __restrict__ dom32) {
    __shared__ int cnt[NEXP];
    __shared__ int flag64;
    int tid = threadIdx.x;
    if (tid < NEXP) cnt[tid] = 0;
    if (tid == 0) flag64 = 1;
    __syncthreads();
    int bad = 0;
    for (int i = tid; i < 4096; i += blockDim.x) {
        int hi = dom32[2 * i + 1];
        int lo = dom32[2 * i];
        if (hi != 0 || lo < 0 || lo > 3) bad = 1;
    }
    if (bad) atomicExch(&flag64, 0);
    __syncthreads();
    bool is64 = (flag64 != 0);
    for (int n = tid; n < N_TOK; n += blockDim.x) {
        int e = is64 ? dom32[2 * n] : dom32[n];
        int pos = atomicAdd(&cnt[e], 1);
        g_idx[e * N_TOK + pos] = n;
    }
    __syncthreads();
    if (tid < NEXP) g_count[tid] = cnt[tid];
}

// ---------------- fp32 -> bf16 hi/lo split pre-pass ------------------------
template <int WHICH>
__global__ void split_kernel(const float* __restrict__ src, int n4) {
    __nv_bfloat16* dh = (WHICH == 0) ? g_xh : (WHICH == 1) ? g_w1h : g_w2h;
    __nv_bfloat16* dl = (WHICH == 0) ? g_xl : (WHICH == 1) ? g_w1l : g_w2l;
    int i = blockIdx.x * blockDim.x + threadIdx.x;
    if (i >= n4) return;
    float4 v = ((const float4*)src)[i];
    __nv_bfloat16 h0 = __float2bfloat16(v.x), h1 = __float2bfloat16(v.y);
    __nv_bfloat16 h2 = __float2bfloat16(v.z), h3 = __float2bfloat16(v.w);
    __nv_bfloat16 l0 = __float2bfloat16(v.x - __bfloat162float(h0));
    __nv_bfloat16 l1 = __float2bfloat16(v.y - __bfloat162float(h1));
    __nv_bfloat16 l2 = __float2bfloat16(v.z - __bfloat162float(h2));
    __nv_bfloat16 l3 = __float2bfloat16(v.w - __bfloat162float(h3));
    ((uint2*)dh)[i] = make_uint2(pack_bf(h0, h1), pack_bf(h2, h3));
    ((uint2*)dl)[i] = make_uint2(pack_bf(l0, l1), pack_bf(l2, l3));
}

// ============================================================================
// Split-bf16 grouped GEMM via mma.sync.  CTA 128x128, 8 warps (4M x 2N),
// warp tile 32x64.  3-term: AhBh + AlBh + AhBl (fp32 accum).
// ============================================================================

// issue one stage of cp.async loads (A gathered by token, B by weight row)
template <int KDIM>
__device__ __forceinline__ void issue_stage(
    char* st, const int* toks_s,
    const __nv_bfloat16* Ah, const __nv_bfloat16* Al,
    const __nv_bfloat16* Bh, const __nv_bfloat16* Bl,
    size_t bbase, int k0, int tid)
{
#pragma unroll
    for (int i = 0; i < 2; i++) {
        int c = tid + i * 256;          // 512 chunks of 16B per tile
        int row = c >> 2, cc = c & 3;
        uint32_t doff = (uint32_t)(row * PAD + cc * 8) * 2;
        int tok = toks_s[row];
        tok = tok < 0 ? 0 : tok;
        size_t aoff = (size_t)tok * KDIM + k0 + cc * 8;
        size_t boff = (bbase + row) * KDIM + k0 + cc * 8;
        cp16(smem_u32(st + 0 * TILEB) + doff, Ah + aoff);
        cp16(smem_u32(st + 1 * TILEB) + doff, Al + aoff);
        cp16(smem_u32(st + 2 * TILEB) + doff, Bh + boff);
        cp16(smem_u32(st + 3 * TILEB) + doff, Bl + boff);
    }
    cp_commit();
}

// compute one stage: 2 x k16 steps, 48 mma per warp per step
__device__ __forceinline__ void compute_stage(
    const char* st, float acc[2][8][4], int wm, int wn, int g, int tg)
{
    const char* sAh = st;
    const char* sAl = st + TILEB;
    const char* sBh = st + 2 * TILEB;
    const char* sBl = st + 3 * TILEB;
#pragma unroll
    for (int ks = 0; ks < 2; ks++) {
        const int Kb = ks * 16;
        uint32_t ah[2][4], al[2][4];
#pragma unroll
        for (int mf = 0; mf < 2; mf++) {
            int R = wm * 32 + mf * 16;
            ah[mf][0] = lpair(sAh, R + g,     Kb + tg * 2);
            ah[mf][1] = lpair(sAh, R + g + 8, Kb + tg * 2);
            ah[mf][2] = lpair(sAh, R + g,     Kb + tg * 2 + 8);
            ah[mf][3] = lpair(sAh, R + g + 8, Kb + tg * 2 + 8);
            al[mf][0] = lpair(sAl, R + g,     Kb + tg * 2);
            al[mf][1] = lpair(sAl, R + g + 8, Kb + tg * 2);
            al[mf][2] = lpair(sAl, R + g,     Kb + tg * 2 + 8);
            al[mf][3] = lpair(sAl, R + g + 8, Kb + tg * 2 + 8);
        }
#pragma unroll
        for (int nf = 0; nf < 8; nf++) {
            int Rn = wn * 64 + nf * 8;
            uint32_t bh[2], bl[2];
            bh[0] = lpair(sBh, Rn + g, Kb + tg * 2);
            bh[1] = lpair(sBh, Rn + g, Kb + tg * 2 + 8);
            bl[0] = lpair(sBl, Rn + g, Kb + tg * 2);
            bl[1] = lpair(sBl, Rn + g, Kb + tg * 2 + 8);
#pragma unroll
            for (int mf = 0; mf < 2; mf++) {
                mma16816(acc[mf][nf], ah[mf], bh);
                mma16816(acc[mf][nf], al[mf], bh);
                mma16816(acc[mf][nf], ah[mf], bl);
            }
        }
    }
}

// ---------------- GEMM1: h = relu(Xg @ W1[e]^T + b1); h split to hi/lo -----
// grid (MDIM/BNT=4, N_TOK/BMT=64, NEXP)
__global__ __launch_bounds__(THREADS, 1)
void gemm1_mma(const float* __restrict__ b1) {
    extern __shared__ char smem[];
    const int e = blockIdx.z;
    const int cnt = g_count[e];
    const int row0 = blockIdx.y * BMT;
    if (row0 >= cnt) return;

    int* toks_s = (int*)smem;
    char* tiles = smem + 1024;
    const int tid = threadIdx.x;
    const int wid = tid >> 5, lane = tid & 31;
    const int wm = wid & 3, wn = wid >> 2;
    const int g = lane >> 2, tg = lane & 3;

    if (tid < BMT) {
        int s = row0 + tid;
        toks_s[tid] = (s < cnt) ? g_idx[e * N_TOK + s] : -1;
    }
    __syncthreads();

    const int n0 = blockIdx.x * BNT;
    const size_t bbase = (size_t)e * MDIM + n0;

    float acc[2][8][4];
#pragma unroll
    for (int mf = 0; mf < 2; mf++)
#pragma unroll
        for (int nf = 0; nf < 8; nf++)
#pragma unroll
            for (int q = 0; q < 4; q++) acc[mf][nf][q] = 0.f;

    const int NIT = DDIM / BK;   // 64
    issue_stage<DDIM>(tiles, toks_s, g_xh, g_xl, g_w1h, g_w1l, bbase, 0, tid);
    for (int it = 0; it < NIT; it++) {
        int s = it & 1;
        if (it + 1 < NIT) {
            issue_stage<DDIM>(tiles + (s ^ 1) * 4 * TILEB, toks_s,
                              g_xh, g_xl, g_w1h, g_w1l, bbase, (it + 1) * BK, tid);
            cp_wait1();
        } else {
            cp_wait0();
        }
        __syncthreads();
        compute_stage(tiles + s * 4 * TILEB, acc, wm, wn, g, tg);
        __syncthreads();
    }

    // epilogue: bias + relu + resplit to bf16 hi/lo
    const float* bb = b1 + (size_t)e * MDIM + n0;
#pragma unroll
    for (int mf = 0; mf < 2; mf++) {
#pragma unroll
        for (int nf = 0; nf < 8; nf++) {
            int col = wn * 64 + nf * 8 + tg * 2;
            float bv0 = bb[col], bv1 = bb[col + 1];
            int r0 = wm * 32 + mf * 16 + g;
#pragma unroll
            for (int half = 0; half < 2; half++) {
                int tok = toks_s[r0 + half * 8];
                if (tok < 0) continue;
                float v0 = fmaxf(acc[mf][nf][half * 2 + 0] + bv0, 0.f);
                float v1 = fmaxf(acc[mf][nf][half * 2 + 1] + bv1, 0.f);
                __nv_bfloat16 h0 = __float2bfloat16(v0);
                __nv_bfloat16 h1 = __float2bfloat16(v1);
                __nv_bfloat16 l0 = __float2bfloat16(v0 - __bfloat162float(h0));
                __nv_bfloat16 l1 = __float2bfloat16(v1 - __bfloat162float(h1));
                size_t off = (size_t)tok * MDIM + n0 + col;
                *(uint32_t*)(g_hh + off) = pack_bf(h0, h1);
                *(uint32_t*)(g_hl + off) = pack_bf(l0, l1);
            }
        }
    }
}

// ---------------- GEMM2: out = x + h @ W2[e]^T + b2 ------------------------
// grid (DDIM/BNT=16, N_TOK/BMT=64, NEXP)
__global__ __launch_bounds__(THREADS, 1)
void gemm2_mma(const float* __restrict__ x, const float* __restrict__ b2,
               float* __restrict__ out) {
    extern __shared__ char smem[];
    const int e = blockIdx.z;
    const int cnt = g_count[e];
    const int row0 = blockIdx.y * BMT;
    if (row0 >= cnt) return;

    int* toks_s = (int*)smem;
    char* tiles = smem + 1024;
    const int tid = threadIdx.x;
    const int wid = tid >> 5, lane = tid & 31;
    const int wm = wid & 3, wn = wid >> 2;
    const int g = lane >> 2, tg = lane & 3;

    if (tid < BMT) {
        int s = row0 + tid;
        toks_s[tid] = (s < cnt) ? g_idx[e * N_TOK + s] : -1;
    }
    __syncthreads();

    const int n0 = blockIdx.x * BNT;
    const size_t bbase = (size_t)e * DDIM + n0;

    float acc[2][8][4];
#pragma unroll
    for (int mf = 0; mf < 2; mf++)
#pragma unroll
        for (int nf = 0; nf < 8; nf++)
#pragma unroll
            for (int q = 0; q < 4; q++) acc[mf][nf][q] = 0.f;

    const int NIT = MDIM / BK;   // 16
    issue_stage<MDIM>(tiles, toks_s, g_hh, g_hl, g_w2h, g_w2l, bbase, 0, tid);
    for (int it = 0; it < NIT; it++) {
        int s = it & 1;
        if (it + 1 < NIT) {
            issue_stage<MDIM>(tiles + (s ^ 1) * 4 * TILEB, toks_s,
                              g_hh, g_hl, g_w2h, g_w2l, bbase, (it + 1) * BK, tid);
            cp_wait1();
        } else {
            cp_wait0();
        }
        __syncthreads();
        compute_stage(tiles + s * 4 * TILEB, acc, wm, wn, g, tg);
        __syncthreads();
    }

    // epilogue: + bias + residual x, fp32 out
    const float* bb = b2 + (size_t)e * DDIM + n0;
#pragma unroll
    for (int mf = 0; mf < 2; mf++) {
#pragma unroll
        for (int nf = 0; nf < 8; nf++) {
            int col = wn * 64 + nf * 8 + tg * 2;
            float bv0 = bb[col], bv1 = bb[col + 1];
            int r0 = wm * 32 + mf * 16 + g;
#pragma unroll
            for (int half = 0; half < 2; half++) {
                int tok = toks_s[r0 + half * 8];
                if (tok < 0) continue;
                size_t off = (size_t)tok * DDIM + n0 + col;
                float2 xv = *(const float2*)(x + off);
                float2 o;
                o.x = acc[mf][nf][half * 2 + 0] + bv0 + xv.x;
                o.y = acc[mf][nf][half * 2 + 1] + bv1 + xv.y;
                *(float2*)(out + off) = o;
            }
        }
    }
}

// ---------------- launch ----------------------------------------------------
extern "C" void kernel_launch(void* const* d_in, const int* in_sizes, int n_in,
                              void* d_out, int out_size) {
    const float* x   = (const float*)d_in[0];
    const int*   dom = (const int*)d_in[1];
    const float* W1  = (const float*)d_in[2];
    const float* b1  = (const float*)d_in[3];
    const float* W2  = (const float*)d_in[4];
    const float* b2  = (const float*)d_in[5];
    float* out = (float*)d_out;

    cudaFuncSetAttribute(gemm1_mma, cudaFuncAttributeMaxDynamicSharedMemorySize, SMEM_BYTES);
    cudaFuncSetAttribute(gemm2_mma, cudaFuncAttributeMaxDynamicSharedMemorySize, SMEM_BYTES);

    bin_kernel<<<1, 256>>>(dom);
    split_kernel<0><<<(N_TOK * DDIM / 4 + 255) / 256, 256>>>(x, N_TOK * DDIM / 4);
    split_kernel<1><<<(NEXP * MDIM * DDIM / 4 + 255) / 256, 256>>>(W1, NEXP * MDIM * DDIM / 4);
    split_kernel<2><<<(NEXP * DDIM * MDIM / 4 + 255) / 256, 256>>>(W2, NEXP * DDIM * MDIM / 4);
    gemm1_mma<<<dim3(MDIM / BNT, N_TOK / BMT, NEXP), THREADS, SMEM_BYTES>>>(b1);
    gemm2_mma<<<dim3(DDIM / BNT, N_TOK / BMT, NEXP), THREADS, SMEM_BYTES>>>(x, b2, out);
}

// round 7
// speedup vs baseline: 2.0588x; 1.0003x over previous
#include <cuda_runtime.h>
#include <cuda_bf16.h>
#include <cstdint>

#define N_TOK 8192
#define DDIM  2048
#define MDIM  512
#define NEXP  4

#define BMT 128           // token rows per CTA
#define BNT 128           // output cols per CTA
#define BK  32            // K elems per stage
#define PAD 40            // padded smem row length (elems) -> conflict-free frags
#define TILEB (128 * PAD * 2)   // bytes per tile (10240)
#define NSTAGE 3
#define THREADS 256
#define SMEM_BYTES (1024 + NSTAGE * 4 * TILEB)   // 123904

// ---------------- device scratch (no cudaMalloc allowed) -------------------
__device__ int g_count[NEXP];
__device__ int g_idx[NEXP * N_TOK];
__device__ __nv_bfloat16 g_xh[(size_t)N_TOK * DDIM];
__device__ __nv_bfloat16 g_xl[(size_t)N_TOK * DDIM];
__device__ __nv_bfloat16 g_w1h[(size_t)NEXP * MDIM * DDIM];
__device__ __nv_bfloat16 g_w1l[(size_t)NEXP * MDIM * DDIM];
__device__ __nv_bfloat16 g_w2h[(size_t)NEXP * DDIM * MDIM];
__device__ __nv_bfloat16 g_w2l[(size_t)NEXP * DDIM * MDIM];
__device__ __nv_bfloat16 g_hh[(size_t)N_TOK * MDIM];
__device__ __nv_bfloat16 g_hl[(size_t)N_TOK * MDIM];

// ---------------- helpers ---------------------------------------------------
__device__ __forceinline__ uint32_t smem_u32(const void* p) {
    uint32_t a;
    asm("{ .reg .u64 t; cvta.to.shared.u64 t, %1; cvt.u32.u64 %0, t; }"
        : "=r"(a) : "l"(p));
    return a;
}
__device__ __forceinline__ void cp16(uint32_t dst, const void* src) {
    asm volatile("cp.async.cg.shared.global [%0], [%1], 16;"
                 :: "r"(dst), "l"(src) : "memory");
}
__device__ __forceinline__ void cp_commit() {
    asm volatile("cp.async.commit_group;" ::: "memory");
}
__device__ __forceinline__ void cp_wait0() {
    asm volatile("cp.async.wait_group 0;" ::: "memory");
}
__device__ __forceinline__ void cp_wait1() {
    asm volatile("cp.async.wait_group 1;" ::: "memory");
}
__device__ __forceinline__ void cp_wait2() {
    asm volatile("cp.async.wait_group 2;" ::: "memory");
}
// mma.sync m16n8k16 bf16 -> f32 (sm_80+; valid on plain sm_103 target)
__device__ __forceinline__ void mma16816(float* c, const uint32_t* a,
                                         const uint32_t* b) {
    asm volatile(
        "mma.sync.aligned.m16n8k16.row.col.f32.bf16.bf16.f32 "
        "{%0,%1,%2,%3}, {%4,%5,%6,%7}, {%8,%9}, {%0,%1,%2,%3};"
        : "+f"(c[0]), "+f"(c[1]), "+f"(c[2]), "+f"(c[3])
        : "r"(a[0]), "r"(a[1]), "r"(a[2]), "r"(a[3]), "r"(b[0]), "r"(b[1]));
}
__device__ __forceinline__ void ldsm4(uint32_t& r0, uint32_t& r1, uint32_t& r2,
                                      uint32_t& r3, uint32_t a) {
    asm volatile("ldmatrix.sync.aligned.m8n8.x4.shared.b16 {%0,%1,%2,%3}, [%4];"
                 : "=r"(r0), "=r"(r1), "=r"(r2), "=r"(r3) : "r"(a));
}
__device__ __forceinline__ uint32_t pack_bf(__nv_bfloat16 a, __nv_bfloat16 b) {
    return (uint32_t)__bfloat16_as_ushort(a) | ((uint32_t)__bfloat16_as_ushort(b) << 16);
}

// ---------------- binning (domains dtype auto-detect) ----------------------
__global__ void bin_kernel(const int* __restrict__ dom32) {
    __shared__ int cnt[NEXP];
    __shared__ int flag64;
    int tid = threadIdx.x;
    if (tid < NEXP) cnt[tid] = 0;
    if (tid == 0) flag64 = 1;
    __syncthreads();
    int bad = 0;
    for (int i = tid; i < 4096; i += blockDim.x) {
        int hi = dom32[2 * i + 1];
        int lo = dom32[2 * i];
        if (hi != 0 || lo < 0 || lo > 3) bad = 1;
    }
    if (bad) atomicExch(&flag64, 0);
    __syncthreads();
    bool is64 = (flag64 != 0);
    for (int n = tid; n < N_TOK; n += blockDim.x) {
        int e = is64 ? dom32[2 * n] : dom32[n];
        int pos = atomicAdd(&cnt[e], 1);
        g_idx[e * N_TOK + pos] = n;
    }
    __syncthreads();
    if (tid < NEXP) g_count[tid] = cnt[tid];
}

// ---------------- fp32 -> bf16 hi/lo split (one launch, 3 segments) --------
__global__ void split_all(const float* __restrict__ x,
                          const float* __restrict__ W1,
                          const float* __restrict__ W2) {
    int seg = blockIdx.y;
    const float* src = (seg == 0) ? x : (seg == 1) ? W1 : W2;
    __nv_bfloat16* dh = (seg == 0) ? g_xh : (seg == 1) ? g_w1h : g_w2h;
    __nv_bfloat16* dl = (seg == 0) ? g_xl : (seg == 1) ? g_w1l : g_w2l;
    int n4 = (seg == 0) ? N_TOK * DDIM / 4 : NEXP * MDIM * DDIM / 4;
    int i = blockIdx.x * blockDim.x + threadIdx.x;
    if (i >= n4) return;
    float4 v = ((const float4*)src)[i];
    __nv_bfloat16 h0 = __float2bfloat16(v.x), h1 = __float2bfloat16(v.y);
    __nv_bfloat16 h2 = __float2bfloat16(v.z), h3 = __float2bfloat16(v.w);
    __nv_bfloat16 l0 = __float2bfloat16(v.x - __bfloat162float(h0));
    __nv_bfloat16 l1 = __float2bfloat16(v.y - __bfloat162float(h1));
    __nv_bfloat16 l2 = __float2bfloat16(v.z - __bfloat162float(h2));
    __nv_bfloat16 l3 = __float2bfloat16(v.w - __bfloat162float(h3));
    ((uint2*)dh)[i] = make_uint2(pack_bf(h0, h1), pack_bf(h2, h3));
    ((uint2*)dl)[i] = make_uint2(pack_bf(l0, l1), pack_bf(l2, l3));
}

// ============================================================================
// Split-bf16 grouped GEMM via mma.sync + ldmatrix.  CTA 128x128, 8 warps
// (4M x 2N), warp tile 32x64.  3-term: AhBh + AlBh + AhBl (fp32 accum).
// ============================================================================

template <int KDIM>
__device__ __forceinline__ void issue_stage(
    char* st, const int* toks_s,
    const __nv_bfloat16* Ah, const __nv_bfloat16* Al,
    const __nv_bfloat16* Bh, const __nv_bfloat16* Bl,
    size_t bbase, int k0, int tid)
{
#pragma unroll
    for (int i = 0; i < 2; i++) {
        int c = tid + i * 256;          // 512 chunks of 16B per tile
        int row = c >> 2, cc = c & 3;
        uint32_t doff = (uint32_t)(row * PAD + cc * 8) * 2;
        int tok = toks_s[row];
        tok = tok < 0 ? 0 : tok;
        size_t aoff = (size_t)tok * KDIM + k0 + cc * 8;
        size_t boff = (bbase + row) * KDIM + k0 + cc * 8;
        cp16(smem_u32(st + 0 * TILEB) + doff, Ah + aoff);
        cp16(smem_u32(st + 1 * TILEB) + doff, Al + aoff);
        cp16(smem_u32(st + 2 * TILEB) + doff, Bh + boff);
        cp16(smem_u32(st + 3 * TILEB) + doff, Bl + boff);
    }
    cp_commit();
}

// compute one stage via ldmatrix: 24 ldmatrix.x4 + 96 mma per warp
__device__ __forceinline__ void compute_stage(
    uint32_t st, float acc[2][8][4], uint32_t aoff, uint32_t boff)
{
    const uint32_t sAh = st, sAl = st + TILEB;
    const uint32_t sBh = st + 2 * TILEB, sBl = st + 3 * TILEB;
#pragma unroll
    for (int ks = 0; ks < 2; ks++) {
        const uint32_t kb = ks * 32;   // 16 elems * 2B
        uint32_t ah[2][4], al[2][4];
#pragma unroll
        for (int mf = 0; mf < 2; mf++) {
            uint32_t off = aoff + kb + mf * (16 * PAD * 2);
            ldsm4(ah[mf][0], ah[mf][1], ah[mf][2], ah[mf][3], sAh + off);
            ldsm4(al[mf][0], al[mf][1], al[mf][2], al[mf][3], sAl + off);
        }
#pragma unroll
        for (int np = 0; np < 4; np++) {
            uint32_t off = boff + kb + np * (16 * PAD * 2);
            uint32_t bh[4], bl[4];
            ldsm4(bh[0], bh[1], bh[2], bh[3], sBh + off);
            ldsm4(bl[0], bl[1], bl[2], bl[3], sBl + off);
#pragma unroll
            for (int hn = 0; hn < 2; hn++) {
                int nf = np * 2 + hn;
#pragma unroll
                for (int mf = 0; mf < 2; mf++) {
                    mma16816(acc[mf][nf], ah[mf], bh + hn * 2);
                    mma16816(acc[mf][nf], al[mf], bh + hn * 2);
                    mma16816(acc[mf][nf], ah[mf], bl + hn * 2);
                }
            }
        }
    }
}

// A-lane ldmatrix offset: rows R+(lane&15), col (lane>>4)*8
__device__ __forceinline__ uint32_t a_lane_off(int wm, int lane) {
    return ((uint32_t)(wm * 32 + (lane & 15)) * PAD + ((lane >> 4) * 8)) * 2;
}
// B-lane ldmatrix offset: rows Rn+(lane&7)+((lane>>4)*8), col ((lane>>3)&1)*8
__device__ __forceinline__ uint32_t b_lane_off(int wn, int lane) {
    return ((uint32_t)(wn * 64 + (lane & 7) + ((lane >> 4) * 8)) * PAD
            + (((lane >> 3) & 1) * 8)) * 2;
}

// ---------------- GEMM1: h = relu(Xg @ W1[e]^T + b1); h split to hi/lo -----
__global__ __launch_bounds__(THREADS, 1)
void gemm1_mma(const float* __restrict__ b1) {
    extern __shared__ char smem[];
    const int e = blockIdx.z;
    const int cnt = g_count[e];
    const int row0 = blockIdx.y * BMT;
    if (row0 >= cnt) return;

    int* toks_s = (int*)smem;
    char* tiles = smem + 1024;
    const uint32_t tiles_u = smem_u32(tiles);
    const int tid = threadIdx.x;
    const int wid = tid >> 5, lane = tid & 31;
    const int wm = wid & 3, wn = wid >> 2;
    const int g = lane >> 2, tg = lane & 3;
    const uint32_t aoff = a_lane_off(wm, lane);
    const uint32_t boff = b_lane_off(wn, lane);

    if (tid < BMT) {
        int s = row0 + tid;
        toks_s[tid] = (s < cnt) ? g_idx[e * N_TOK + s] : -1;
    }
    __syncthreads();

    const int n0 = blockIdx.x * BNT;
    const size_t bbase = (size_t)e * MDIM + n0;

    float acc[2][8][4];
#pragma unroll
    for (int mf = 0; mf < 2; mf++)
#pragma unroll
        for (int nf = 0; nf < 8; nf++)
#pragma unroll
            for (int q = 0; q < 4; q++) acc[mf][nf][q] = 0.f;

    const int NIT = DDIM / BK;   // 64
    issue_stage<DDIM>(tiles, toks_s, g_xh, g_xl, g_w1h, g_w1l, bbase, 0, tid);
    issue_stage<DDIM>(tiles + 4 * TILEB, toks_s, g_xh, g_xl, g_w1h, g_w1l,
                      bbase, BK, tid);
    for (int it = 0; it < NIT; it++) {
        if (it + 2 < NIT) {
            issue_stage<DDIM>(tiles + ((it + 2) % NSTAGE) * 4 * TILEB, toks_s,
                              g_xh, g_xl, g_w1h, g_w1l, bbase, (it + 2) * BK, tid);
            cp_wait2();
        } else if (it + 1 < NIT) {
            cp_wait1();
        } else {
            cp_wait0();
        }
        __syncthreads();
        compute_stage(tiles_u + (it % NSTAGE) * 4 * TILEB, acc, aoff, boff);
        __syncthreads();
    }

    // epilogue: bias + relu + resplit to bf16 hi/lo
    const float* bb = b1 + (size_t)e * MDIM + n0;
#pragma unroll
    for (int mf = 0; mf < 2; mf++) {
#pragma unroll
        for (int nf = 0; nf < 8; nf++) {
            int col = wn * 64 + nf * 8 + tg * 2;
            float bv0 = bb[col], bv1 = bb[col + 1];
            int r0 = wm * 32 + mf * 16 + g;
#pragma unroll
            for (int half = 0; half < 2; half++) {
                int tok = toks_s[r0 + half * 8];
                if (tok < 0) continue;
                float v0 = fmaxf(acc[mf][nf][half * 2 + 0] + bv0, 0.f);
                float v1 = fmaxf(acc[mf][nf][half * 2 + 1] + bv1, 0.f);
                __nv_bfloat16 h0 = __float2bfloat16(v0);
                __nv_bfloat16 h1 = __float2bfloat16(v1);
                __nv_bfloat16 l0 = __float2bfloat16(v0 - __bfloat162float(h0));
                __nv_bfloat16 l1 = __float2bfloat16(v1 - __bfloat162float(h1));
                size_t off = (size_t)tok * MDIM + n0 + col;
                *(uint32_t*)(g_hh + off) = pack_bf(h0, h1);
                *(uint32_t*)(g_hl + off) = pack_bf(l0, l1);
            }
        }
    }
}

// ---------------- GEMM2: out = x + h @ W2[e]^T + b2 ------------------------
__global__ __launch_bounds__(THREADS, 1)
void gemm2_mma(const float* __restrict__ x, const float* __restrict__ b2,
               float* __restrict__ out) {
    extern __shared__ char smem[];
    const int e = blockIdx.z;
    const int cnt = g_count[e];
    const int row0 = blockIdx.y * BMT;
    if (row0 >= cnt) return;

    int* toks_s = (int*)smem;
    char* tiles = smem + 1024;
    const uint32_t tiles_u = smem_u32(tiles);
    const int tid = threadIdx.x;
    const int wid = tid >> 5, lane = tid & 31;
    const int wm = wid & 3, wn = wid >> 2;
    const int g = lane >> 2, tg = lane & 3;
    const uint32_t aoff = a_lane_off(wm, lane);
    const uint32_t boff = b_lane_off(wn, lane);

    if (tid < BMT) {
        int s = row0 + tid;
        toks_s[tid] = (s < cnt) ? g_idx[e * N_TOK + s] : -1;
    }
    __syncthreads();

    const int n0 = blockIdx.x * BNT;
    const size_t bbase = (size_t)e * DDIM + n0;

    float acc[2][8][4];
#pragma unroll
    for (int mf = 0; mf < 2; mf++)
#pragma unroll
        for (int nf = 0; nf < 8; nf++)
#pragma unroll
            for (int q = 0; q < 4; q++) acc[mf][nf][q] = 0.f;

    const int NIT = MDIM / BK;   // 16
    issue_stage<MDIM>(tiles, toks_s, g_hh, g_hl, g_w2h, g_w2l, bbase, 0, tid);
    issue_stage<MDIM>(tiles + 4 * TILEB, toks_s, g_hh, g_hl, g_w2h, g_w2l,
                      bbase, BK, tid);
    for (int it = 0; it < NIT; it++) {
        if (it + 2 < NIT) {
            issue_stage<MDIM>(tiles + ((it + 2) % NSTAGE) * 4 * TILEB, toks_s,
                              g_hh, g_hl, g_w2h, g_w2l, bbase, (it + 2) * BK, tid);
            cp_wait2();
        } else if (it + 1 < NIT) {
            cp_wait1();
        } else {
            cp_wait0();
        }
        __syncthreads();
        compute_stage(tiles_u + (it % NSTAGE) * 4 * TILEB, acc, aoff, boff);
        __syncthreads();
    }

    // epilogue: + bias + residual x, fp32 out
    const float* bb = b2 + (size_t)e * DDIM + n0;
#pragma unroll
    for (int mf = 0; mf < 2; mf++) {
#pragma unroll
        for (int nf = 0; nf < 8; nf++) {
            int col = wn * 64 + nf * 8 + tg * 2;
            float bv0 = bb[col], bv1 = bb[col + 1];
            int r0 = wm * 32 + mf * 16 + g;
#pragma unroll
            for (int half = 0; half < 2; half++) {
                int tok = toks_s[r0 + half * 8];
                if (tok < 0) continue;
                size_t off = (size_t)tok * DDIM + n0 + col;
                float2 xv = *(const float2*)(x + off);
                float2 o;
                o.x = acc[mf][nf][half * 2 + 0] + bv0 + xv.x;
                o.y = acc[mf][nf][half * 2 + 1] + bv1 + xv.y;
                *(float2*)(out + off) = o;
            }
        }
    }
}

// ---------------- launch ----------------------------------------------------
extern "C" void kernel_launch(void* const* d_in, const int* in_sizes, int n_in,
                              void* d_out, int out_size) {
    const float* x   = (const float*)d_in[0];
    const int*   dom = (const int*)d_in[1];
    const float* W1  = (const float*)d_in[2];
    const float* b1  = (const float*)d_in[3];
    const float* W2  = (const float*)d_in[4];
    const float* b2  = (const float*)d_in[5];
    float* out = (float*)d_out;

    cudaFuncSetAttribute(gemm1_mma, cudaFuncAttributeMaxDynamicSharedMemorySize, SMEM_BYTES);
    cudaFuncSetAttribute(gemm2_mma, cudaFuncAttributeMaxDynamicSharedMemorySize, SMEM_BYTES);

    bin_kernel<<<1, 256>>>(dom);
    split_all<<<dim3((N_TOK * DDIM / 4 + 255) / 256, 3), 256>>>(x, W1, W2);
    gemm1_mma<<<dim3(MDIM / BNT, N_TOK / BMT, NEXP), THREADS, SMEM_BYTES>>>(b1);
    gemm2_mma<<<dim3(DDIM / BNT, N_TOK / BMT, NEXP), THREADS, SMEM_BYTES>>>(x, b2, out);
}

// round 16
// speedup vs baseline: 2.0710x; 1.0060x over previous
#include <cuda_runtime.h>
#include <cuda_bf16.h>
#include <cstdint>

#define N_TOK 8192
#define DDIM  2048
#define MDIM  512
#define NEXP  4

#define BMT 128           // token rows per CTA
#define BNT 128           // output cols per CTA
#define BK  32            // K elems per stage
#define PAD 40            // padded smem row length (elems) -> conflict-free frags
#define TILEB (128 * PAD * 2)   // bytes per tile (10240)
#define NSTAGE 3
#define THREADS 512
#define SMEM_BYTES (1024 + NSTAGE * 4 * TILEB)   // 123904

// ---------------- device scratch (no cudaMalloc allowed) -------------------
__device__ int g_count[NEXP];
__device__ int g_idx[NEXP * N_TOK];
__device__ __nv_bfloat16 g_xh[(size_t)N_TOK * DDIM];
__device__ __nv_bfloat16 g_xl[(size_t)N_TOK * DDIM];
__device__ __nv_bfloat16 g_w1h[(size_t)NEXP * MDIM * DDIM];
__device__ __nv_bfloat16 g_w1l[(size_t)NEXP * MDIM * DDIM];
__device__ __nv_bfloat16 g_w2h[(size_t)NEXP * DDIM * MDIM];
__device__ __nv_bfloat16 g_w2l[(size_t)NEXP * DDIM * MDIM];
__device__ __nv_bfloat16 g_hh[(size_t)N_TOK * MDIM];
__device__ __nv_bfloat16 g_hl[(size_t)N_TOK * MDIM];

// ---------------- helpers ---------------------------------------------------
__device__ __forceinline__ uint32_t smem_u32(const void* p) {
    uint32_t a;
    asm("{ .reg .u64 t; cvta.to.shared.u64 t, %1; cvt.u32.u64 %0, t; }"
        : "=r"(a) : "l"(p));
    return a;
}
__device__ __forceinline__ void cp16(uint32_t dst, const void* src) {
    asm volatile("cp.async.cg.shared.global [%0], [%1], 16;"
                 :: "r"(dst), "l"(src) : "memory");
}
__device__ __forceinline__ void cp_commit() {
    asm volatile("cp.async.commit_group;" ::: "memory");
}
__device__ __forceinline__ void cp_wait0() {
    asm volatile("cp.async.wait_group 0;" ::: "memory");
}
__device__ __forceinline__ void cp_wait1() {
    asm volatile("cp.async.wait_group 1;" ::: "memory");
}
// mma.sync m16n8k16 bf16 -> f32 (sm_80+; valid on plain sm_103 target)
__device__ __forceinline__ void mma16816(float* c, const uint32_t* a,
                                         const uint32_t* b) {
    asm volatile(
        "mma.sync.aligned.m16n8k16.row.col.f32.bf16.bf16.f32 "
        "{%0,%1,%2,%3}, {%4,%5,%6,%7}, {%8,%9}, {%0,%1,%2,%3};"
        : "+f"(c[0]), "+f"(c[1]), "+f"(c[2]), "+f"(c[3])
        : "r"(a[0]), "r"(a[1]), "r"(a[2]), "r"(a[3]), "r"(b[0]), "r"(b[1]));
}
__device__ __forceinline__ void ldsm4(uint32_t& r0, uint32_t& r1, uint32_t& r2,
                                      uint32_t& r3, uint32_t a) {
    asm volatile("ldmatrix.sync.aligned.m8n8.x4.shared.b16 {%0,%1,%2,%3}, [%4];"
                 : "=r"(r0), "=r"(r1), "=r"(r2), "=r"(r3) : "r"(a));
}
__device__ __forceinline__ uint32_t pack_bf(__nv_bfloat16 a, __nv_bfloat16 b) {
    return (uint32_t)__bfloat16_as_ushort(a) | ((uint32_t)__bfloat16_as_ushort(b) << 16);
}

// ---------------- binning (domains dtype auto-detect) ----------------------
__global__ void bin_kernel(const int* __restrict__ dom32) {
    __shared__ int cnt[NEXP];
    __shared__ int flag64;
    int tid = threadIdx.x;
    if (tid < NEXP) cnt[tid] = 0;
    if (tid == 0) flag64 = 1;
    __syncthreads();
    int bad = 0;
    for (int i = tid; i < 4096; i += blockDim.x) {
        int hi = dom32[2 * i + 1];
        int lo = dom32[2 * i];
        if (hi != 0 || lo < 0 || lo > 3) bad = 1;
    }
    if (bad) atomicExch(&flag64, 0);
    __syncthreads();
    bool is64 = (flag64 != 0);
    for (int n = tid; n < N_TOK; n += blockDim.x) {
        int e = is64 ? dom32[2 * n] : dom32[n];
        int pos = atomicAdd(&cnt[e], 1);
        g_idx[e * N_TOK + pos] = n;
    }
    __syncthreads();
    if (tid < NEXP) g_count[tid] = cnt[tid];
}

// ---------------- fp32 -> bf16 hi/lo split (one launch, 3 segments) --------
__global__ void split_all(const float* __restrict__ x,
                          const float* __restrict__ W1,
                          const float* __restrict__ W2) {
    int seg = blockIdx.y;
    const float* src = (seg == 0) ? x : (seg == 1) ? W1 : W2;
    __nv_bfloat16* dh = (seg == 0) ? g_xh : (seg == 1) ? g_w1h : g_w2h;
    __nv_bfloat16* dl = (seg == 0) ? g_xl : (seg == 1) ? g_w1l : g_w2l;
    int n4 = (seg == 0) ? N_TOK * DDIM / 4 : NEXP * MDIM * DDIM / 4;
    int i = blockIdx.x * blockDim.x + threadIdx.x;
    if (i >= n4) return;
    float4 v = ((const float4*)src)[i];
    __nv_bfloat16 h0 = __float2bfloat16(v.x), h1 = __float2bfloat16(v.y);
    __nv_bfloat16 h2 = __float2bfloat16(v.z), h3 = __float2bfloat16(v.w);
    __nv_bfloat16 l0 = __float2bfloat16(v.x - __bfloat162float(h0));
    __nv_bfloat16 l1 = __float2bfloat16(v.y - __bfloat162float(h1));
    __nv_bfloat16 l2 = __float2bfloat16(v.z - __bfloat162float(h2));
    __nv_bfloat16 l3 = __float2bfloat16(v.w - __bfloat162float(h3));
    ((uint2*)dh)[i] = make_uint2(pack_bf(h0, h1), pack_bf(h2, h3));
    ((uint2*)dl)[i] = make_uint2(pack_bf(l0, l1), pack_bf(l2, l3));
}

// ============================================================================
// Split-bf16 grouped GEMM via mma.sync + ldmatrix.  CTA 128x128, 16 warps
// (4M x 4N), warp tile 32x32.  3-term: AhBh + AlBh + AhBl (fp32 accum).
// Single __syncthreads per mainloop iteration; cp.async issue before compute.
// ============================================================================

template <int KDIM>
__device__ __forceinline__ void issue_stage(
    char* st, const int* toks_s,
    const __nv_bfloat16* Ah, const __nv_bfloat16* Al,
    const __nv_bfloat16* Bh, const __nv_bfloat16* Bl,
    size_t bbase, int k0, int tid)
{
    // 512 threads, 512 chunks of 16B per tile: each thread does 1 chunk x 4 tiles
    int row = tid >> 2, cc = tid & 3;
    uint32_t doff = (uint32_t)(row * PAD + cc * 8) * 2;
    int tok = toks_s[row];
    tok = tok < 0 ? 0 : tok;
    size_t aoff = (size_t)tok * KDIM + k0 + cc * 8;
    size_t boff = (bbase + row) * KDIM + k0 + cc * 8;
    cp16(smem_u32(st + 0 * TILEB) + doff, Ah + aoff);
    cp16(smem_u32(st + 1 * TILEB) + doff, Al + aoff);
    cp16(smem_u32(st + 2 * TILEB) + doff, Bh + boff);
    cp16(smem_u32(st + 3 * TILEB) + doff, Bl + boff);
    cp_commit();
}

// compute one stage: warp tile 32x32 -> per k16: 4+4 ldsm4, 24 mma
__device__ __forceinline__ void compute_stage(
    uint32_t st, float acc[2][4][4], uint32_t aoff, uint32_t boff)
{
    const uint32_t sAh = st, sAl = st + TILEB;
    const uint32_t sBh = st + 2 * TILEB, sBl = st + 3 * TILEB;
#pragma unroll
    for (int ks = 0; ks < 2; ks++) {
        const uint32_t kb = ks * 32;   // 16 elems * 2B
        uint32_t ah[2][4], al[2][4];
#pragma unroll
        for (int mf = 0; mf < 2; mf++) {
            uint32_t off = aoff + kb + mf * (16 * PAD * 2);
            ldsm4(ah[mf][0], ah[mf][1], ah[mf][2], ah[mf][3], sAh + off);
            ldsm4(al[mf][0], al[mf][1], al[mf][2], al[mf][3], sAl + off);
        }
#pragma unroll
        for (int np = 0; np < 2; np++) {
            uint32_t off = boff + kb + np * (16 * PAD * 2);
            uint32_t bh[4], bl[4];
            ldsm4(bh[0], bh[1], bh[2], bh[3], sBh + off);
            ldsm4(bl[0], bl[1], bl[2], bl[3], sBl + off);
#pragma unroll
            for (int hn = 0; hn < 2; hn++) {
                int nf = np * 2 + hn;
#pragma unroll
                for (int mf = 0; mf < 2; mf++) {
                    mma16816(acc[mf][nf], ah[mf], bh + hn * 2);
                    mma16816(acc[mf][nf], al[mf], bh + hn * 2);
                    mma16816(acc[mf][nf], ah[mf], bl + hn * 2);
                }
            }
        }
    }
}

// A-lane ldmatrix offset: rows R+(lane&15), col (lane>>4)*8
__device__ __forceinline__ uint32_t a_lane_off(int wm, int lane) {
    return ((uint32_t)(wm * 32 + (lane & 15)) * PAD + ((lane >> 4) * 8)) * 2;
}
// B-lane ldmatrix offset: rows Rn+(lane&7)+((lane>>4)*8), col ((lane>>3)&1)*8
__device__ __forceinline__ uint32_t b_lane_off(int wn, int lane) {
    return ((uint32_t)(wn * 32 + (lane & 7) + ((lane >> 4) * 8)) * PAD
            + (((lane >> 3) & 1) * 8)) * 2;
}

// ---------------- GEMM1: h = relu(Xg @ W1[e]^T + b1); h split to hi/lo -----
__global__ __launch_bounds__(THREADS, 1)
void gemm1_mma(const float* __restrict__ b1) {
    extern __shared__ char smem[];
    const int e = blockIdx.z;
    const int cnt = g_count[e];
    const int row0 = blockIdx.y * BMT;
    if (row0 >= cnt) return;

    int* toks_s = (int*)smem;
    char* tiles = smem + 1024;
    const uint32_t tiles_u = smem_u32(tiles);
    const int tid = threadIdx.x;
    const int wid = tid >> 5, lane = tid & 31;
    const int wm = wid & 3, wn = wid >> 2;
    const int g = lane >> 2, tg = lane & 3;
    const uint32_t aoff = a_lane_off(wm, lane);
    const uint32_t boff = b_lane_off(wn, lane);

    if (tid < BMT) {
        int s = row0 + tid;
        toks_s[tid] = (s < cnt) ? g_idx[e * N_TOK + s] : -1;
    }
    __syncthreads();

    const int n0 = blockIdx.x * BNT;
    const size_t bbase = (size_t)e * MDIM + n0;

    float acc[2][4][4];
#pragma unroll
    for (int mf = 0; mf < 2; mf++)
#pragma unroll
        for (int nf = 0; nf < 4; nf++)
#pragma unroll
            for (int q = 0; q < 4; q++) acc[mf][nf][q] = 0.f;

    const int NIT = DDIM / BK;   // 64
    issue_stage<DDIM>(tiles, toks_s, g_xh, g_xl, g_w1h, g_w1l, bbase, 0, tid);
    issue_stage<DDIM>(tiles + 4 * TILEB, toks_s, g_xh, g_xl, g_w1h, g_w1l,
                      bbase, BK, tid);
    for (int it = 0; it < NIT; it++) {
        if (it + 1 < NIT) cp_wait1(); else cp_wait0();
        __syncthreads();   // stage it visible; all warps done with stage it-1
        if (it + 2 < NIT)
            issue_stage<DDIM>(tiles + ((it + 2) % NSTAGE) * 4 * TILEB, toks_s,
                              g_xh, g_xl, g_w1h, g_w1l, bbase, (it + 2) * BK, tid);
        compute_stage(tiles_u + (it % NSTAGE) * 4 * TILEB, acc, aoff, boff);
    }

    // epilogue: bias + relu + resplit to bf16 hi/lo
    const float* bb = b1 + (size_t)e * MDIM + n0;
#pragma unroll
    for (int mf = 0; mf < 2; mf++) {
#pragma unroll
        for (int nf = 0; nf < 4; nf++) {
            int col = wn * 32 + nf * 8 + tg * 2;
            float bv0 = bb[col], bv1 = bb[col + 1];
            int r0 = wm * 32 + mf * 16 + g;
#pragma unroll
            for (int half = 0; half < 2; half++) {
                int tok = toks_s[r0 + half * 8];
                if (tok < 0) continue;
                float v0 = fmaxf(acc[mf][nf][half * 2 + 0] + bv0, 0.f);
                float v1 = fmaxf(acc[mf][nf][half * 2 + 1] + bv1, 0.f);
                __nv_bfloat16 h0 = __float2bfloat16(v0);
                __nv_bfloat16 h1 = __float2bfloat16(v1);
                __nv_bfloat16 l0 = __float2bfloat16(v0 - __bfloat162float(h0));
                __nv_bfloat16 l1 = __float2bfloat16(v1 - __bfloat162float(h1));
                size_t off = (size_t)tok * MDIM + n0 + col;
                *(uint32_t*)(g_hh + off) = pack_bf(h0, h1);
                *(uint32_t*)(g_hl + off) = pack_bf(l0, l1);
            }
        }
    }
}

// ---------------- GEMM2: out = x + h @ W2[e]^T + b2 ------------------------
__global__ __launch_bounds__(THREADS, 1)
void gemm2_mma(const float* __restrict__ x, const float* __restrict__ b2,
               float* __restrict__ out) {
    extern __shared__ char smem[];
    const int e = blockIdx.z;
    const int cnt = g_count[e];
    const int row0 = blockIdx.y * BMT;
    if (row0 >= cnt) return;

    int* toks_s = (int*)smem;
    char* tiles = smem + 1024;
    const uint32_t tiles_u = smem_u32(tiles);
    const int tid = threadIdx.x;
    const int wid = tid >> 5, lane = tid & 31;
    const int wm = wid & 3, wn = wid >> 2;
    const int g = lane >> 2, tg = lane & 3;
    const uint32_t aoff = a_lane_off(wm, lane);
    const uint32_t boff = b_lane_off(wn, lane);

    if (tid < BMT) {
        int s = row0 + tid;
        toks_s[tid] = (s < cnt) ? g_idx[e * N_TOK + s] : -1;
    }
    __syncthreads();

    const int n0 = blockIdx.x * BNT;
    const size_t bbase = (size_t)e * DDIM + n0;

    float acc[2][4][4];
#pragma unroll
    for (int mf = 0; mf < 2; mf++)
#pragma unroll
        for (int nf = 0; nf < 4; nf++)
#pragma unroll
            for (int q = 0; q < 4; q++) acc[mf][nf][q] = 0.f;

    const int NIT = MDIM / BK;   // 16
    issue_stage<MDIM>(tiles, toks_s, g_hh, g_hl, g_w2h, g_w2l, bbase, 0, tid);
    issue_stage<MDIM>(tiles + 4 * TILEB, toks_s, g_hh, g_hl, g_w2h, g_w2l,
                      bbase, BK, tid);
    for (int it = 0; it < NIT; it++) {
        if (it + 1 < NIT) cp_wait1(); else cp_wait0();
        __syncthreads();
        if (it + 2 < NIT)
            issue_stage<MDIM>(tiles + ((it + 2) % NSTAGE) * 4 * TILEB, toks_s,
                              g_hh, g_hl, g_w2h, g_w2l, bbase, (it + 2) * BK, tid);
        compute_stage(tiles_u + (it % NSTAGE) * 4 * TILEB, acc, aoff, boff);
    }

    // epilogue: + bias + residual x, fp32 out
    const float* bb = b2 + (size_t)e * DDIM + n0;
#pragma unroll
    for (int mf = 0; mf < 2; mf++) {
#pragma unroll
        for (int nf = 0; nf < 4; nf++) {
            int col = wn * 32 + nf * 8 + tg * 2;
            float bv0 = bb[col], bv1 = bb[col + 1];
            int r0 = wm * 32 + mf * 16 + g;
#pragma unroll
            for (int half = 0; half < 2; half++) {
                int tok = toks_s[r0 + half * 8];
                if (tok < 0) continue;
                size_t off = (size_t)tok * DDIM + n0 + col;
                float2 xv = *(const float2*)(x + off);
                float2 o;
                o.x = acc[mf][nf][half * 2 + 0] + bv0 + xv.x;
                o.y = acc[mf][nf][half * 2 + 1] + bv1 + xv.y;
                *(float2*)(out + off) = o;
            }
        }
    }
}

// ---------------- launch ----------------------------------------------------
extern "C" void kernel_launch(void* const* d_in, const int* in_sizes, int n_in,
                              void* d_out, int out_size) {
    const float* x   = (const float*)d_in[0];
    const int*   dom = (const int*)d_in[1];
    const float* W1  = (const float*)d_in[2];
    const float* b1  = (const float*)d_in[3];
    const float* W2  = (const float*)d_in[4];
    const float* b2  = (const float*)d_in[5];
    float* out = (float*)d_out;

    cudaFuncSetAttribute(gemm1_mma, cudaFuncAttributeMaxDynamicSharedMemorySize, SMEM_BYTES);
    cudaFuncSetAttribute(gemm2_mma, cudaFuncAttributeMaxDynamicSharedMemorySize, SMEM_BYTES);

    bin_kernel<<<1, 256>>>(dom);
    split_all<<<dim3((N_TOK * DDIM / 4 + 255) / 256, 3), 256>>>(x, W1, W2);
    gemm1_mma<<<dim3(MDIM / BNT, N_TOK / BMT, NEXP), THREADS, SMEM_BYTES>>>(b1);
    gemm2_mma<<<dim3(DDIM / BNT, N_TOK / BMT, NEXP), THREADS, SMEM_BYTES>>>(x, b2, out);
}